// round 8
// baseline (speedup 1.0000x reference)
#include <cuda_runtime.h>
#include <float.h>

// Fused sRGB->CIELab + per-image L min-max normalization, single kernel,
// cross-CTA per-image sync (8 CTAs/image). R8: R7's math schedule (all heavy
// math pre-sync, trivial phase2) at R6's occupancy (7 CTAs/SM via
// launch_bounds + scalar smem stores to kill live ranges).

#define NPIX    16384
#define NIMG    512
#define SUBS    8
#define THREADS 256
#define PX_CTA  (NPIX / SUBS)          // 2048
#define NG_CTA  (PX_CTA / 4)           // 512 groups of 4 px
#define GROUPS  (NG_CTA / THREADS)     // 2 per thread

__device__ float g_pmin[NIMG * SUBS];
__device__ float g_pmax[NIMG * SUBS];
__device__ int   g_arrive[NIMG];       // zero-init; self-reset each launch
__device__ int   g_done[NIMG];         // zero-init; self-reset each launch

__device__ __forceinline__ float mufu_lg2(float x) {
    float r; asm("lg2.approx.f32 %0, %1;" : "=f"(r) : "f"(x)); return r;
}
__device__ __forceinline__ float mufu_ex2(float x) {
    float r; asm("ex2.approx.f32 %0, %1;" : "=f"(r) : "f"(x)); return r;
}
__device__ __forceinline__ float mufu_rcp(float x) {
    float r; asm("rcp.approx.f32 %0, %1;" : "=f"(r) : "f"(x)); return r;
}

__device__ __forceinline__ float srgb_lin(float c) {
    float t = fmaf(c, 1.0f / 1.055f, 0.055f / 1.055f);
    float p = mufu_ex2(2.4f * mufu_lg2(t));
    return (c > 0.04045f) ? p : c * (1.0f / 12.92f);
}

__device__ __forceinline__ float xyz_f(float t) {
    float cr = mufu_ex2((1.0f / 3.0f) * mufu_lg2(t));
    return (t > 0.008856f) ? cr : fmaf(t, 7.787f, 16.0f / 116.0f);
}

__global__ void __launch_bounds__(THREADS, 7)
rgb2lab_sync_kernel(const float* __restrict__ x, float* __restrict__ out) {
    __shared__ float sA[PX_CTA];       // 8KB  a01 (scalar-indexed)
    __shared__ float sB[PX_CTA];       // 8KB  b01
    __shared__ float sF[PX_CTA];       // 8KB  fy
    __shared__ float red[18];

    const int bid = blockIdx.x;
    const int img = bid >> 3;
    const int tid = threadIdx.x;

    const int base4 = bid * (PX_CTA * 3 / 4);
    const float4* in4 = (const float4*)x   + base4;
    float4*       o4  = (float4*)      out + base4;

    float mnA = FLT_MAX, mnB = FLT_MAX;
    float mxA = -FLT_MAX, mxB = -FLT_MAX;

    const float M00 = 0.412453f / 0.95047f, M01 = 0.357580f / 0.95047f, M02 = 0.180423f / 0.95047f;
    const float M10 = 0.212671f,            M11 = 0.715160f,            M12 = 0.072169f;
    const float M20 = 0.019334f / 1.08883f, M21 = 0.119193f / 1.08883f, M22 = 0.950227f / 1.08883f;

    // ---------------- phase 1: ALL heavy math, scalar stash ---------------
    #pragma unroll
    for (int j = 0; j < GROUPS; j++) {
        int gi = tid + j * THREADS;
        float4 v0 = __ldcs(&in4[gi * 3 + 0]);
        float4 v1 = __ldcs(&in4[gi * 3 + 1]);
        float4 v2 = __ldcs(&in4[gi * 3 + 2]);
        int p = gi * 4;

        // pixel 0
        {
            float rl = srgb_lin(v0.x), gl = srgb_lin(v0.y), bl = srgb_lin(v0.z);
            float fx = xyz_f(fmaf(M00, rl, fmaf(M01, gl, M02 * bl)));
            float fy = xyz_f(fmaf(M10, rl, fmaf(M11, gl, M12 * bl)));
            float fz = xyz_f(fmaf(M20, rl, fmaf(M21, gl, M22 * bl)));
            sA[p] = fmaf(fx - fy, 500.0f / 255.0f, 128.0f / 255.0f);
            sB[p] = fmaf(fy - fz, 200.0f / 255.0f, 128.0f / 255.0f);
            sF[p] = fy;
            mnA = fminf(mnA, fy);  mxA = fmaxf(mxA, fy);
        }
        // pixel 1
        {
            float rl = srgb_lin(v0.w), gl = srgb_lin(v1.x), bl = srgb_lin(v1.y);
            float fx = xyz_f(fmaf(M00, rl, fmaf(M01, gl, M02 * bl)));
            float fy = xyz_f(fmaf(M10, rl, fmaf(M11, gl, M12 * bl)));
            float fz = xyz_f(fmaf(M20, rl, fmaf(M21, gl, M22 * bl)));
            sA[p + 1] = fmaf(fx - fy, 500.0f / 255.0f, 128.0f / 255.0f);
            sB[p + 1] = fmaf(fy - fz, 200.0f / 255.0f, 128.0f / 255.0f);
            sF[p + 1] = fy;
            mnB = fminf(mnB, fy);  mxB = fmaxf(mxB, fy);
        }
        // pixel 2
        {
            float rl = srgb_lin(v1.z), gl = srgb_lin(v1.w), bl = srgb_lin(v2.x);
            float fx = xyz_f(fmaf(M00, rl, fmaf(M01, gl, M02 * bl)));
            float fy = xyz_f(fmaf(M10, rl, fmaf(M11, gl, M12 * bl)));
            float fz = xyz_f(fmaf(M20, rl, fmaf(M21, gl, M22 * bl)));
            sA[p + 2] = fmaf(fx - fy, 500.0f / 255.0f, 128.0f / 255.0f);
            sB[p + 2] = fmaf(fy - fz, 200.0f / 255.0f, 128.0f / 255.0f);
            sF[p + 2] = fy;
            mnA = fminf(mnA, fy);  mxA = fmaxf(mxA, fy);
        }
        // pixel 3
        {
            float rl = srgb_lin(v2.y), gl = srgb_lin(v2.z), bl = srgb_lin(v2.w);
            float fx = xyz_f(fmaf(M00, rl, fmaf(M01, gl, M02 * bl)));
            float fy = xyz_f(fmaf(M10, rl, fmaf(M11, gl, M12 * bl)));
            float fz = xyz_f(fmaf(M20, rl, fmaf(M21, gl, M22 * bl)));
            sA[p + 3] = fmaf(fx - fy, 500.0f / 255.0f, 128.0f / 255.0f);
            sB[p + 3] = fmaf(fy - fz, 200.0f / 255.0f, 128.0f / 255.0f);
            sF[p + 3] = fy;
            mnB = fminf(mnB, fy);  mxB = fmaxf(mxB, fy);
        }
    }
    float fmn = fminf(mnA, mnB);
    float fmx = fmaxf(mxA, mxB);

    // ---------------- CTA-local reduce (8 warps) --------------------------
    #pragma unroll
    for (int off = 16; off > 0; off >>= 1) {
        fmn = fminf(fmn, __shfl_xor_sync(0xffffffffu, fmn, off));
        fmx = fmaxf(fmx, __shfl_xor_sync(0xffffffffu, fmx, off));
    }
    int lane = tid & 31, wid = tid >> 5;
    if (lane == 0) { red[wid] = fmn; red[8 + wid] = fmx; }
    __syncthreads();

    // ---------------- publish partial + spin + self-reset -----------------
    if (tid == 0) {
        float mn = red[0], mx = red[8];
        #pragma unroll
        for (int i = 1; i < 8; i++) {
            mn = fminf(mn, red[i]);
            mx = fmaxf(mx, red[8 + i]);
        }
        g_pmin[bid] = mn;
        g_pmax[bid] = mx;
        asm volatile("red.release.gpu.global.add.s32 [%0], 1;"
                     :: "l"(&g_arrive[img]) : "memory");

        int c;
        do {
            asm volatile("ld.acquire.gpu.global.s32 %0, [%1];"
                         : "=r"(c) : "l"(&g_arrive[img]) : "memory");
            if (c < SUBS) __nanosleep(64);
        } while (c < SUBS);

        float fm = FLT_MAX, fM = -FLT_MAX;
        #pragma unroll
        for (int i = 0; i < SUBS; i++) {
            fm = fminf(fm, g_pmin[img * 8 + i]);
            fM = fmaxf(fM, g_pmax[img * 8 + i]);
        }
        red[16] = fm;
        red[17] = mufu_rcp(fM - fm);

        int prev = atomicAdd(&g_done[img], 1);
        if (prev == SUBS - 1) {
            g_arrive[img] = 0;
            g_done[img]   = 0;
        }
    }
    __syncthreads();
    const float fmin = red[16];
    const float sf   = red[17];

    // ---------------- phase 2: trivial normalize + store ------------------
    const float4* sA4 = (const float4*)sA;
    const float4* sB4 = (const float4*)sB;
    const float4* sF4 = (const float4*)sF;

    #pragma unroll
    for (int j = 0; j < GROUPS; j++) {
        int gi = tid + j * THREADS;
        float4 a4 = sA4[gi];
        float4 b4 = sB4[gi];
        float4 f4 = sF4[gi];

        float L0 = (f4.x - fmin) * sf;
        float L1 = (f4.y - fmin) * sf;
        float L2 = (f4.z - fmin) * sf;
        float L3 = (f4.w - fmin) * sf;

        __stcs(&o4[gi * 3 + 0], make_float4(L0,   a4.x, b4.x, L1));
        __stcs(&o4[gi * 3 + 1], make_float4(a4.y, b4.y, L2,   a4.z));
        __stcs(&o4[gi * 3 + 2], make_float4(b4.z, L3,   a4.w, b4.w));
    }
}

extern "C" void kernel_launch(void* const* d_in, const int* in_sizes, int n_in,
                              void* d_out, int out_size) {
    const float* x   = (const float*)d_in[0];
    float*       out = (float*)d_out;

    rgb2lab_sync_kernel<<<NIMG * SUBS, THREADS>>>(x, out);
}

// round 9
// speedup vs baseline: 1.0362x; 1.0362x over previous
#include <cuda_runtime.h>
#include <float.h>

// Fused sRGB->CIELab + per-image L min-max normalization, single kernel with
// cross-CTA per-image sync. 8 CTAs per image (R6 structure — best measured):
//   phase1 (LIGHT, pre-sync): read own 2048 px ONCE (__ldcs), linearize
//          (6 MUFU/px), stash lin RGB in smem, publish Y min/max partial fast.
//   spin  : thread0 acquire-spins until all 8 partials landed.
//   phase2 (HEAVY, post-sync): matrix + 3 cbrt from own smem, coalesced writes.
// Self-resetting arrive/done counters -> no memset graph node.

#define NPIX    16384
#define NIMG    512
#define SUBS    8                      // CTAs per image
#define THREADS 256
#define PX_CTA  (NPIX / SUBS)          // 2048 px per CTA
#define NG_CTA  (PX_CTA / 4)           // 512 pixel-groups per CTA
#define GROUPS  (NG_CTA / THREADS)     // 2 groups per thread

__device__ float g_pmin[NIMG * SUBS];
__device__ float g_pmax[NIMG * SUBS];
__device__ int   g_arrive[NIMG];       // zero-init; self-reset each launch
__device__ int   g_done[NIMG];         // zero-init; self-reset each launch

__device__ __forceinline__ float mufu_lg2(float x) {
    float r; asm("lg2.approx.f32 %0, %1;" : "=f"(r) : "f"(x)); return r;
}
__device__ __forceinline__ float mufu_ex2(float x) {
    float r; asm("ex2.approx.f32 %0, %1;" : "=f"(r) : "f"(x)); return r;
}
__device__ __forceinline__ float mufu_rcp(float x) {
    float r; asm("rcp.approx.f32 %0, %1;" : "=f"(r) : "f"(x)); return r;
}

__device__ __forceinline__ float srgb_lin(float c) {
    float t = fmaf(c, 1.0f / 1.055f, 0.055f / 1.055f);
    float p = mufu_ex2(2.4f * mufu_lg2(t));
    return (c > 0.04045f) ? p : c * (1.0f / 12.92f);
}

__device__ __forceinline__ float xyz_f(float t) {
    float cr = mufu_ex2((1.0f / 3.0f) * mufu_lg2(t));
    return (t > 0.008856f) ? cr : fmaf(t, 7.787f, 16.0f / 116.0f);
}

__global__ void __launch_bounds__(THREADS, 8)
rgb2lab_sync_kernel(const float* __restrict__ x, float* __restrict__ out) {
    __shared__ float4 sR[NG_CTA];      // 8KB  linearized R plane
    __shared__ float4 sG[NG_CTA];      // 8KB
    __shared__ float4 sB[NG_CTA];      // 8KB
    __shared__ float  red[18];         // 8 warp-mins, 8 warp-maxs, fmin, sf

    const int bid = blockIdx.x;
    const int img = bid >> 3;
    const int tid = threadIdx.x;

    const int base4 = bid * (PX_CTA * 3 / 4);
    const float4* in4 = (const float4*)x   + base4;
    float4*       o4  = (float4*)      out + base4;

    float ymin = FLT_MAX, ymax = -FLT_MAX;

    // ---------------- phase 1 (LIGHT): read once, linearize, stash --------
    #pragma unroll
    for (int j = 0; j < GROUPS; j++) {
        int gi = tid + j * THREADS;                // 0 .. 511
        float4 v0 = __ldcs(&in4[gi * 3 + 0]);
        float4 v1 = __ldcs(&in4[gi * 3 + 1]);
        float4 v2 = __ldcs(&in4[gi * 3 + 2]);

        float4 r4 = make_float4(srgb_lin(v0.x), srgb_lin(v0.w), srgb_lin(v1.z), srgb_lin(v2.y));
        float4 g4 = make_float4(srgb_lin(v0.y), srgb_lin(v1.x), srgb_lin(v1.w), srgb_lin(v2.z));
        float4 b4 = make_float4(srgb_lin(v0.z), srgb_lin(v1.y), srgb_lin(v2.x), srgb_lin(v2.w));

        sR[gi] = r4;  sG[gi] = g4;  sB[gi] = b4;

        float y0 = fmaf(0.212671f, r4.x, fmaf(0.715160f, g4.x, 0.072169f * b4.x));
        float y1 = fmaf(0.212671f, r4.y, fmaf(0.715160f, g4.y, 0.072169f * b4.y));
        float y2 = fmaf(0.212671f, r4.z, fmaf(0.715160f, g4.z, 0.072169f * b4.z));
        float y3 = fmaf(0.212671f, r4.w, fmaf(0.715160f, g4.w, 0.072169f * b4.w));
        ymin = fminf(fminf(fminf(ymin, y0), fminf(y1, y2)), y3);
        ymax = fmaxf(fmaxf(fmaxf(ymax, y0), fmaxf(y1, y2)), y3);
    }

    // ---------------- CTA-local reduce (8 warps) --------------------------
    #pragma unroll
    for (int off = 16; off > 0; off >>= 1) {
        ymin = fminf(ymin, __shfl_xor_sync(0xffffffffu, ymin, off));
        ymax = fmaxf(ymax, __shfl_xor_sync(0xffffffffu, ymax, off));
    }
    int lane = tid & 31, wid = tid >> 5;
    if (lane == 0) { red[wid] = ymin; red[8 + wid] = ymax; }
    __syncthreads();

    // ---------------- publish partial + spin + self-reset -----------------
    if (tid == 0) {
        float mn = red[0], mx = red[8];
        #pragma unroll
        for (int i = 1; i < 8; i++) {
            mn = fminf(mn, red[i]);
            mx = fmaxf(mx, red[8 + i]);
        }
        g_pmin[bid] = mn;
        g_pmax[bid] = mx;
        asm volatile("red.release.gpu.global.add.s32 [%0], 1;"
                     :: "l"(&g_arrive[img]) : "memory");

        int c;
        do {
            asm volatile("ld.acquire.gpu.global.s32 %0, [%1];"
                         : "=r"(c) : "l"(&g_arrive[img]) : "memory");
            if (c < SUBS) __nanosleep(64);
        } while (c < SUBS);

        float fm = FLT_MAX, fM = -FLT_MAX;
        #pragma unroll
        for (int i = 0; i < SUBS; i++) {
            fm = fminf(fm, g_pmin[img * 8 + i]);
            fM = fmaxf(fM, g_pmax[img * 8 + i]);
        }
        float fmn = xyz_f(fm);
        red[16] = fmn;
        red[17] = mufu_rcp(xyz_f(fM) - fmn);

        // self-reset: last CTA past the spin zeroes both counters
        int prev = atomicAdd(&g_done[img], 1);
        if (prev == SUBS - 1) {
            g_arrive[img] = 0;
            g_done[img]   = 0;
        }
    }
    __syncthreads();
    const float fmin = red[16];
    const float sf   = red[17];

    // ---------------- phase 2 (HEAVY): matrix + cbrt + write --------------
    const float M00 = 0.412453f / 0.95047f, M01 = 0.357580f / 0.95047f, M02 = 0.180423f / 0.95047f;
    const float M10 = 0.212671f,            M11 = 0.715160f,            M12 = 0.072169f;
    const float M20 = 0.019334f / 1.08883f, M21 = 0.119193f / 1.08883f, M22 = 0.950227f / 1.08883f;

    #pragma unroll
    for (int j = 0; j < GROUPS; j++) {
        int gi = tid + j * THREADS;
        float4 r4 = sR[gi];
        float4 g4 = sG[gi];
        float4 b4 = sB[gi];

        float L[4], A[4], B[4];
        const float* rr = &r4.x; const float* gg = &g4.x; const float* bb = &b4.x;
        #pragma unroll
        for (int p = 0; p < 4; p++) {
            float rl = rr[p], gl = gg[p], bl = bb[p];
            float X = fmaf(M00, rl, fmaf(M01, gl, M02 * bl));
            float Y = fmaf(M10, rl, fmaf(M11, gl, M12 * bl));
            float Z = fmaf(M20, rl, fmaf(M21, gl, M22 * bl));
            float fx = xyz_f(X);
            float fy = xyz_f(Y);
            float fz = xyz_f(Z);
            L[p] = (fy - fmin) * sf;
            A[p] = fmaf(fx - fy, 500.0f / 255.0f, 128.0f / 255.0f);
            B[p] = fmaf(fy - fz, 200.0f / 255.0f, 128.0f / 255.0f);
        }

        o4[gi * 3 + 0] = make_float4(L[0], A[0], B[0], L[1]);
        o4[gi * 3 + 1] = make_float4(A[1], B[1], L[2], A[2]);
        o4[gi * 3 + 2] = make_float4(B[2], L[3], A[3], B[3]);
    }
}

extern "C" void kernel_launch(void* const* d_in, const int* in_sizes, int n_in,
                              void* d_out, int out_size) {
    const float* x   = (const float*)d_in[0];
    float*       out = (float*)d_out;

    rgb2lab_sync_kernel<<<NIMG * SUBS, THREADS>>>(x, out);
}